// round 5
// baseline (speedup 1.0000x reference)
#include <cuda_runtime.h>
#include <math.h>

#define NA 8192
#define NV 4096
#define NN 12288      // NA + NV
#define FDIM 64
#define ADIM 128
#define KAA 10
#define KVV 15
#define MAXDEG 30
#define LTOT 8
#define OUTD 128

// ---------------- device scratch (no allocations allowed) ----------------
__device__ float g_h[NN * ADIM];
__device__ float g_voxh0[NV * ADIM];
__device__ float g_q[NN * ADIM];
__device__ float g_k[NN * ADIM];
__device__ float g_v[NN * ADIM];
__device__ int   g_aa[NA * KAA];
__device__ int   g_av[NV * KVV];
__device__ int   g_vv[NV * KVV];
__device__ int   g_Uidx[NN * MAXDEG];
__device__ float g_Uew[NN * MAXDEG];
__device__ float g_paas[NA * 8];
__device__ float g_paad[NA * 8];
__device__ float g_pavd[NV * 8];
__device__ float g_pavs[NA * 8];
__device__ float g_pvvs[NV * 8];
__device__ float g_pvvd[NV * 8];
__device__ float g_bo[4 * NV * ADIM];
__device__ float g_feat[NV * 640];
__device__ float g_hidden[NV * ADIM];

// ---------------- generic tiled GEMM: C[M,N] = A[M,K] @ B[K,N] (+bias)(+relu)
// grid = (M/64, N/64), block = 256 threads, each thread 4x4 outputs
__global__ void gemm64(const float* __restrict__ A, const float* __restrict__ B,
                       const float* __restrict__ bias, float* __restrict__ C,
                       int K, int N, int doRelu)
{
    __shared__ __align__(16) float As[16][64];
    __shared__ __align__(16) float Bs[16][64];
    int tid = threadIdx.x;
    int tx = tid & 15, ty = tid >> 4;
    int bm = blockIdx.x << 6, bn = blockIdx.y << 6;
    int arow = tid >> 2, acol = (tid & 3) << 2;
    int brow = tid >> 4, bcol = (tid & 15) << 2;
    const float* Ap = A + (size_t)(bm + arow) * K + acol;
    const float* Bp = B + (size_t)brow * N + bn + bcol;

    float acc00=0,acc01=0,acc02=0,acc03=0;
    float acc10=0,acc11=0,acc12=0,acc13=0;
    float acc20=0,acc21=0,acc22=0,acc23=0;
    float acc30=0,acc31=0,acc32=0,acc33=0;

    for (int k0 = 0; k0 < K; k0 += 16) {
        float4 avv = *(const float4*)(Ap + k0);
        float4 bvv = *(const float4*)(Bp + (size_t)k0 * N);
        As[acol + 0][arow] = avv.x;
        As[acol + 1][arow] = avv.y;
        As[acol + 2][arow] = avv.z;
        As[acol + 3][arow] = avv.w;
        *(float4*)(&Bs[brow][bcol]) = bvv;
        __syncthreads();
#pragma unroll
        for (int kk = 0; kk < 16; ++kk) {
            float4 a = *(const float4*)(&As[kk][ty << 2]);
            float4 b = *(const float4*)(&Bs[kk][tx << 2]);
            acc00 = fmaf(a.x, b.x, acc00); acc01 = fmaf(a.x, b.y, acc01);
            acc02 = fmaf(a.x, b.z, acc02); acc03 = fmaf(a.x, b.w, acc03);
            acc10 = fmaf(a.y, b.x, acc10); acc11 = fmaf(a.y, b.y, acc11);
            acc12 = fmaf(a.y, b.z, acc12); acc13 = fmaf(a.y, b.w, acc13);
            acc20 = fmaf(a.z, b.x, acc20); acc21 = fmaf(a.z, b.y, acc21);
            acc22 = fmaf(a.z, b.z, acc22); acc23 = fmaf(a.z, b.w, acc23);
            acc30 = fmaf(a.w, b.x, acc30); acc31 = fmaf(a.w, b.y, acc31);
            acc32 = fmaf(a.w, b.z, acc32); acc33 = fmaf(a.w, b.w, acc33);
        }
        __syncthreads();
    }

    float accs[4][4] = {{acc00,acc01,acc02,acc03},{acc10,acc11,acc12,acc13},
                        {acc20,acc21,acc22,acc23},{acc30,acc31,acc32,acc33}};
#pragma unroll
    for (int i = 0; i < 4; ++i) {
        int r = bm + (ty << 2) + i;
#pragma unroll
        for (int j = 0; j < 4; ++j) {
            int c = bn + (tx << 2) + j;
            float vv = accs[i][j];
            if (bias) vv += bias[c];
            if (doRelu) vv = fmaxf(vv, 0.f);
            C[(size_t)r * N + c] = vv;
        }
    }
}

// ---------------- simple copy ----------------
__global__ void copy_kernel(const float* __restrict__ src, float* __restrict__ dst, int n)
{
    int i = blockIdx.x * blockDim.x + threadIdx.x;
    if (i < n) dst[i] = src[i];
}

// ---------------- brute-force KNN: warp per dst, smem-tiled src positions
// reproduces reference d2 = |a|^2 + |b|^2 - 2 a.b and top_k stable (d2, idx) ordering
template <int KK, bool EXCL>
__global__ void knn_kernel(const float* __restrict__ dpos, const float* __restrict__ spos,
                           int Ns, int* __restrict__ outIdx)
{
    const int TS = 1024;
    __shared__ float sx[TS], sy[TS], sz[TS];
    int lane = threadIdx.x & 31;
    int dst = (blockIdx.x << 3) + (threadIdx.x >> 5);

    float px = dpos[dst * 3 + 0], py = dpos[dst * 3 + 1], pz = dpos[dst * 3 + 2];
    float sa = px * px + py * py + pz * pz;

    float bd[KK]; int bi[KK];
#pragma unroll
    for (int p = 0; p < KK; ++p) { bd[p] = 3.0e38f; bi[p] = 0x7fffffff; }

    for (int t0 = 0; t0 < Ns; t0 += TS) {
        int tn = Ns - t0; if (tn > TS) tn = TS;
        __syncthreads();
        for (int i = threadIdx.x; i < tn; i += 256) {
            sx[i] = spos[(t0 + i) * 3 + 0];
            sy[i] = spos[(t0 + i) * 3 + 1];
            sz[i] = spos[(t0 + i) * 3 + 2];
        }
        __syncthreads();
        for (int j = lane; j < tn; j += 32) {
            int si = t0 + j;
            if (EXCL && si == dst) continue;
            float qx = sx[j], qy = sy[j], qz = sz[j];
            float sb = qx * qx + qy * qy + qz * qz;
            float dot = fmaf(pz, qz, fmaf(py, qy, px * qx));
            float d2 = (sa + sb) - 2.0f * dot;
            if (d2 < bd[KK - 1] || (d2 == bd[KK - 1] && si < bi[KK - 1])) {
                bd[KK - 1] = d2; bi[KK - 1] = si;
#pragma unroll
                for (int p = KK - 1; p > 0; --p) {
                    bool sw = (bd[p] < bd[p - 1]) || (bd[p] == bd[p - 1] && bi[p] < bi[p - 1]);
                    if (sw) {
                        float td = bd[p]; bd[p] = bd[p - 1]; bd[p - 1] = td;
                        int   ti = bi[p]; bi[p] = bi[p - 1]; bi[p - 1] = ti;
                    }
                }
            }
        }
    }
    // warp merge of 32 sorted lane lists -> global KK smallest (lexicographic)
    for (int r = 0; r < KK; ++r) {
        float cd = bd[0]; int ci = bi[0]; int cl = lane;
#pragma unroll
        for (int off = 16; off > 0; off >>= 1) {
            float od = __shfl_xor_sync(0xffffffffu, cd, off);
            int oi = __shfl_xor_sync(0xffffffffu, ci, off);
            int ol = __shfl_xor_sync(0xffffffffu, cl, off);
            if (od < cd || (od == cd && oi < ci)) { cd = od; ci = oi; cl = ol; }
        }
        if (lane == 0) outIdx[dst * KK + r] = ci;
        if (lane == cl) {
#pragma unroll
            for (int p = 0; p < KK - 1; ++p) { bd[p] = bd[p + 1]; bi[p] = bi[p + 1]; }
            bd[KK - 1] = 3.0e38f; bi[KK - 1] = 0x7fffffff;
        }
    }
}

// ---------------- per-row 128->8 projection (edge MLP first layer halves)
// warp per row; W is [128,8] row-major slice (row stride 8)
__global__ void proj8_kernel(const float* __restrict__ H, int Nrows,
                             const float* __restrict__ W, float* __restrict__ out)
{
    int w = (blockIdx.x * blockDim.x + threadIdx.x) >> 5;
    int lane = threadIdx.x & 31;
    if (w >= Nrows) return;
    const float* hr = H + (size_t)w * ADIM;
    float acc[8];
#pragma unroll
    for (int m = 0; m < 8; ++m) acc[m] = 0.f;
    for (int f = lane; f < ADIM; f += 32) {
        float hv = hr[f];
        const float* wr = W + f * 8;
#pragma unroll
        for (int m = 0; m < 8; ++m) acc[m] = fmaf(hv, wr[m], acc[m]);
    }
#pragma unroll
    for (int off = 16; off > 0; off >>= 1) {
#pragma unroll
        for (int m = 0; m < 8; ++m) acc[m] += __shfl_xor_sync(0xffffffffu, acc[m], off);
    }
    if (lane == 0) {
#pragma unroll
        for (int m = 0; m < 8; ++m) out[w * 8 + m] = acc[m];
    }
}

// ---------------- edge weight MLP (decomposed) + unified neighbor table write
__global__ void edgew_kernel(const int* __restrict__ nbr, int E, int Kk,
                             const float* __restrict__ dstPos, const float* __restrict__ srcPos,
                             const float* __restrict__ pSrc, const float* __restrict__ pDst,
                             const float* __restrict__ w1d, const float* __restrict__ b1,
                             const float* __restrict__ w2, const float* __restrict__ b2v,
                             int* __restrict__ Uidx, float* __restrict__ Uew,
                             int dstNodeBase, int slotOff, int srcGlobalOff)
{
    int e = blockIdx.x * blockDim.x + threadIdx.x;
    if (e >= E) return;
    int dl = e / Kk, slot = e - dl * Kk;
    int s = nbr[e];
    float dx = dstPos[dl * 3 + 0] - srcPos[s * 3 + 0];
    float dy = dstPos[dl * 3 + 1] - srcPos[s * 3 + 1];
    float dz = dstPos[dl * 3 + 2] - srcPos[s * 3 + 2];
    float ss = fmaf(dz, dz, fmaf(dy, dy, dx * dx));
    float d = sqrtf(ss + 1e-12f);
    float ew = b2v[0];
#pragma unroll
    for (int m = 0; m < 8; ++m) {
        float hmid = pSrc[s * 8 + m] + pDst[dl * 8 + m] + d * w1d[m] + b1[m];
        ew = fmaf(fmaxf(hmid, 0.f), w2[m], ew);
    }
    int un = dstNodeBase + dl;
    Uidx[un * MAXDEG + slotOff + slot] = srcGlobalOff + s;
    Uew[un * MAXDEG + slotOff + slot] = ew;
}

// ---------------- fused attention + residual + LayerNorm (+optional snapshot)
// one block (128 threads = 4 head-warps) per dst node
__global__ void attn_kernel(const float* __restrict__ q, const float* __restrict__ k,
                            const float* __restrict__ v,
                            const int* __restrict__ Uidx, const float* __restrict__ Uew,
                            float* __restrict__ h,
                            const float* __restrict__ lng, const float* __restrict__ lnb,
                            float* __restrict__ snap)
{
    __shared__ float kvs[MAXDEG][133];
    __shared__ float qs[ADIM];
    __shared__ int   srcs[MAXDEG];
    __shared__ float ews[MAXDEG];
    __shared__ float red[8];

    int n = blockIdx.x;
    int t = threadIdx.x;
    int head = t >> 5, lane = t & 31;
    int deg = (n < NA) ? KAA : MAXDEG;

    if (t < deg) { srcs[t] = Uidx[n * MAXDEG + t]; ews[t] = Uew[n * MAXDEG + t]; }
    qs[t] = q[(size_t)n * ADIM + t];
    __syncthreads();

    // stage k rows of all neighbors (coalesced)
#pragma unroll 4
    for (int j = 0; j < deg; ++j) kvs[j][t] = k[(size_t)srcs[j] * ADIM + t];
    __syncthreads();

    // logits: lane j of each head-warp handles neighbor j
    float logit = -3.0e38f;
    if (lane < deg) {
        const float* kr = &kvs[lane][head << 5];
        const float* qr = &qs[head << 5];
        float acc = 0.f;
#pragma unroll
        for (int d = 0; d < 32; ++d) acc = fmaf(kr[d], qr[d], acc);
        logit = acc * 0.17677669529663687f + ews[lane];
    }
    float m = logit;
#pragma unroll
    for (int off = 16; off > 0; off >>= 1)
        m = fmaxf(m, __shfl_xor_sync(0xffffffffu, m, off));
    float z = (lane < deg) ? expf(logit - m) : 0.f;
    float ssum = z;
#pragma unroll
    for (int off = 16; off > 0; off >>= 1)
        ssum += __shfl_xor_sync(0xffffffffu, ssum, off);
    float alpha = z / (ssum + 1e-9f);

    __syncthreads();  // before reusing kvs for v
#pragma unroll 4
    for (int j = 0; j < deg; ++j) kvs[j][t] = v[(size_t)srcs[j] * ADIM + t];
    __syncthreads();

    float acc = 0.f;
    for (int j = 0; j < deg; ++j) {
        float a = __shfl_sync(0xffffffffu, alpha, j);
        acc = fmaf(a, kvs[j][(head << 5) + lane], acc);
    }

    // residual + LN
    float y = h[(size_t)n * ADIM + t] + acc;
    float s1 = y, s2 = y * y;
#pragma unroll
    for (int off = 16; off > 0; off >>= 1) {
        s1 += __shfl_xor_sync(0xffffffffu, s1, off);
        s2 += __shfl_xor_sync(0xffffffffu, s2, off);
    }
    if (lane == 0) { red[head] = s1; red[4 + head] = s2; }
    __syncthreads();
    float t1 = red[0] + red[1] + red[2] + red[3];
    float t2 = red[4] + red[5] + red[6] + red[7];
    float mu = t1 * (1.0f / ADIM);
    float var = fmaxf(t2 * (1.0f / ADIM) - mu * mu, 0.f);
    float outv = (y - mu) * rsqrtf(var + 1e-5f) * lng[t] + lnb[t];
    h[(size_t)n * ADIM + t] = outv;
    if (snap != nullptr && n >= NA) snap[(size_t)(n - NA) * ADIM + t] = outv;
}

// ---------------- feat assembly: [vox_h0 | bo0 | bo1 | bo2 | bo3]
__global__ void feat_kernel(const float* __restrict__ voxh0,
                            const float* __restrict__ b0, const float* __restrict__ b1,
                            const float* __restrict__ b2, const float* __restrict__ b3,
                            float* __restrict__ feat)
{
    int i = blockIdx.x * blockDim.x + threadIdx.x;
    if (i >= NV * 640) return;
    int r = i / 640, c = i - r * 640;
    int seg = c >> 7, cc = c & 127;
    const float* s = (seg == 0) ? voxh0 : (seg == 1) ? b0 : (seg == 2) ? b1 : (seg == 3) ? b2 : b3;
    feat[i] = s[(size_t)r * ADIM + cc];
}

// ---------------- host ----------------
extern "C" void kernel_launch(void* const* d_in, const int* in_sizes, int n_in,
                              void* d_out, int out_size)
{
    const float* atom_x    = (const float*)d_in[0];
    const float* atom_pos  = (const float*)d_in[1];
    const float* vox_x     = (const float*)d_in[2];
    const float* vox_pos   = (const float*)d_in[3];
    const float* w_atom_in = (const float*)d_in[4];
    const float* b_atom_in = (const float*)d_in[5];
    const float* w_vox_in  = (const float*)d_in[6];
    const float* b_vox_in  = (const float*)d_in[7];
    const float* aa_w1 = (const float*)d_in[8];
    const float* aa_b1 = (const float*)d_in[9];
    const float* aa_w2 = (const float*)d_in[10];
    const float* aa_b2 = (const float*)d_in[11];
    const float* av_w1 = (const float*)d_in[12];
    const float* av_b1 = (const float*)d_in[13];
    const float* av_w2 = (const float*)d_in[14];
    const float* av_b2 = (const float*)d_in[15];
    const float* vv_w1 = (const float*)d_in[16];
    const float* vv_b1 = (const float*)d_in[17];
    const float* vv_w2 = (const float*)d_in[18];
    const float* vv_b2 = (const float*)d_in[19];
    const float* wq   = (const float*)d_in[20];
    const float* wk   = (const float*)d_in[21];
    const float* wv   = (const float*)d_in[22];
    const float* ln_g = (const float*)d_in[23];
    const float* ln_b = (const float*)d_in[24];
    const float* w_o1 = (const float*)d_in[25];
    const float* b_o1 = (const float*)d_in[26];
    const float* w_o2 = (const float*)d_in[27];
    const float* b_o2 = (const float*)d_in[28];
    float* out = (float*)d_out;
    (void)in_sizes; (void)n_in; (void)out_size;

    float *h, *voxh0, *q, *k, *v, *Uew, *paas, *paad, *pavd, *pavs, *pvvs, *pvvd, *bo, *feat, *hidden;
    int *aaIdx, *avIdx, *vvIdx, *Uidx;
    cudaGetSymbolAddress((void**)&h, g_h);
    cudaGetSymbolAddress((void**)&voxh0, g_voxh0);
    cudaGetSymbolAddress((void**)&q, g_q);
    cudaGetSymbolAddress((void**)&k, g_k);
    cudaGetSymbolAddress((void**)&v, g_v);
    cudaGetSymbolAddress((void**)&aaIdx, g_aa);
    cudaGetSymbolAddress((void**)&avIdx, g_av);
    cudaGetSymbolAddress((void**)&vvIdx, g_vv);
    cudaGetSymbolAddress((void**)&Uidx, g_Uidx);
    cudaGetSymbolAddress((void**)&Uew, g_Uew);
    cudaGetSymbolAddress((void**)&paas, g_paas);
    cudaGetSymbolAddress((void**)&paad, g_paad);
    cudaGetSymbolAddress((void**)&pavd, g_pavd);
    cudaGetSymbolAddress((void**)&pavs, g_pavs);
    cudaGetSymbolAddress((void**)&pvvs, g_pvvs);
    cudaGetSymbolAddress((void**)&pvvd, g_pvvd);
    cudaGetSymbolAddress((void**)&bo, g_bo);
    cudaGetSymbolAddress((void**)&feat, g_feat);
    cudaGetSymbolAddress((void**)&hidden, g_hidden);

    // 1) input projections -> h (atoms then voxels), keep vox_h0 copy
    gemm64<<<dim3(NA / 64, ADIM / 64), 256>>>(atom_x, w_atom_in, b_atom_in, h, FDIM, ADIM, 0);
    gemm64<<<dim3(NV / 64, ADIM / 64), 256>>>(vox_x, w_vox_in, b_vox_in, h + (size_t)NA * ADIM, FDIM, ADIM, 0);
    copy_kernel<<<(NV * ADIM + 255) / 256, 256>>>(h + (size_t)NA * ADIM, voxh0, NV * ADIM);

    // 2) KNN graphs
    knn_kernel<KAA, true><<<NA / 8, 256>>>(atom_pos, atom_pos, NA, aaIdx);
    knn_kernel<KVV, false><<<NV / 8, 256>>>(vox_pos, atom_pos, NA, avIdx);
    knn_kernel<KVV, true><<<NV / 8, 256>>>(vox_pos, vox_pos, NV, vvIdx);

    // 3) edge-MLP first-layer projections (top half = i0 features, bottom = i1)
    proj8_kernel<<<NA / 8, 256>>>(h, NA, aa_w1, paas);                 // aa: i0 = src atom
    proj8_kernel<<<NA / 8, 256>>>(h, NA, aa_w1 + 128 * 8, paad);       // aa: i1 = dst atom
    proj8_kernel<<<NV / 8, 256>>>(voxh0, NV, av_w1, pavd);             // av: i0 = vox (dst)
    proj8_kernel<<<NA / 8, 256>>>(h, NA, av_w1 + 128 * 8, pavs);       // av: i1 = atom (src)
    proj8_kernel<<<NV / 8, 256>>>(voxh0, NV, vv_w1, pvvs);             // vv: i0 = src vox
    proj8_kernel<<<NV / 8, 256>>>(voxh0, NV, vv_w1 + 128 * 8, pvvd);   // vv: i1 = dst vox

    // 4) edge weights + unified neighbor table
    edgew_kernel<<<(NA * KAA + 255) / 256, 256>>>(aaIdx, NA * KAA, KAA, atom_pos, atom_pos,
        paas, paad, aa_w1 + 256 * 8, aa_b1, aa_w2, aa_b2, Uidx, Uew, 0, 0, 0);
    edgew_kernel<<<(NV * KVV + 255) / 256, 256>>>(avIdx, NV * KVV, KVV, vox_pos, atom_pos,
        pavs, pavd, av_w1 + 256 * 8, av_b1, av_w2, av_b2, Uidx, Uew, NA, 0, 0);
    edgew_kernel<<<(NV * KVV + 255) / 256, 256>>>(vvIdx, NV * KVV, KVV, vox_pos, vox_pos,
        pvvs, pvvd, vv_w1 + 256 * 8, vv_b1, vv_w2, vv_b2, Uidx, Uew, NA, KVV, NA);

    // 5) attention stack (8 layers), snapshot vox part after each block
    for (int li = 0; li < LTOT; ++li) {
        const float* Wq = wq + (size_t)li * ADIM * ADIM;
        const float* Wk = wk + (size_t)li * ADIM * ADIM;
        const float* Wv = wv + (size_t)li * ADIM * ADIM;
        gemm64<<<dim3(NN / 64, ADIM / 64), 256>>>(h, Wq, nullptr, q, ADIM, ADIM, 0);
        gemm64<<<dim3(NN / 64, ADIM / 64), 256>>>(h, Wk, nullptr, k, ADIM, ADIM, 0);
        gemm64<<<dim3(NN / 64, ADIM / 64), 256>>>(h, Wv, nullptr, v, ADIM, ADIM, 0);
        float* snap = (li & 1) ? (bo + (size_t)(li >> 1) * NV * ADIM) : nullptr;
        attn_kernel<<<NN, 128>>>(q, k, v, Uidx, Uew, h,
                                 ln_g + (size_t)li * ADIM, ln_b + (size_t)li * ADIM, snap);
    }

    // 6) output head
    feat_kernel<<<(NV * 640 + 255) / 256, 256>>>(voxh0,
        bo, bo + (size_t)NV * ADIM, bo + (size_t)2 * NV * ADIM, bo + (size_t)3 * NV * ADIM, feat);
    gemm64<<<dim3(NV / 64, ADIM / 64), 256>>>(feat, w_o1, b_o1, hidden, 640, ADIM, 1);
    gemm64<<<dim3(NV / 64, OUTD / 64), 256>>>(hidden, w_o2, b_o2, out, ADIM, OUTD, 0);
}

// round 6
// speedup vs baseline: 1.0441x; 1.0441x over previous
#include <cuda_runtime.h>
#include <math.h>

#define NA 8192
#define NV 4096
#define NN 12288      // NA + NV
#define FDIM 64
#define ADIM 128
#define QKVS 384
#define KAA 10
#define KVV 15
#define MAXDEG 30
#define LTOT 8
#define OUTD 128

// ---------------- device scratch (no allocations allowed) ----------------
__device__ float  g_h[NN * ADIM];
__device__ float  g_qkv[NN * QKVS];
__device__ float  g_wqkv[LTOT * ADIM * QKVS];
__device__ float4 g_apos4[NA];
__device__ float4 g_vpos4[NV];
__device__ int    g_aa[NA * KAA];
__device__ int    g_av[NV * KVV];
__device__ int    g_vv[NV * KVV];
__device__ int    g_Uidx[NN * MAXDEG];
__device__ float  g_Uew[NN * MAXDEG];
__device__ float  g_paas[NA * 8];
__device__ float  g_paad[NA * 8];
__device__ float  g_pavd[NV * 8];
__device__ float  g_pavs[NA * 8];
__device__ float  g_pvvs[NV * 8];
__device__ float  g_pvvd[NV * 8];
__device__ float  g_feat[NV * 640];
__device__ float  g_hidden[NV * ADIM];

// ---------------- generic tiled GEMM: C[M,N] = A[M,K] @ B[K,N] (+bias)(+relu)
// grid = (M/64, N/64), block = 256 threads, each thread 4x4 outputs
__global__ void gemm64(const float* __restrict__ A, const float* __restrict__ B,
                       const float* __restrict__ bias, float* __restrict__ C,
                       int K, int N, int doRelu, int ldc)
{
    __shared__ __align__(16) float As[16][64];
    __shared__ __align__(16) float Bs[16][64];
    int tid = threadIdx.x;
    int tx = tid & 15, ty = tid >> 4;
    int bm = blockIdx.x << 6, bn = blockIdx.y << 6;
    int arow = tid >> 2, acol = (tid & 3) << 2;
    int brow = tid >> 4, bcol = (tid & 15) << 2;
    const float* Ap = A + (size_t)(bm + arow) * K + acol;
    const float* Bp = B + (size_t)brow * N + bn + bcol;

    float acc00=0,acc01=0,acc02=0,acc03=0;
    float acc10=0,acc11=0,acc12=0,acc13=0;
    float acc20=0,acc21=0,acc22=0,acc23=0;
    float acc30=0,acc31=0,acc32=0,acc33=0;

    for (int k0 = 0; k0 < K; k0 += 16) {
        float4 avv = *(const float4*)(Ap + k0);
        float4 bvv = *(const float4*)(Bp + (size_t)k0 * N);
        As[acol + 0][arow] = avv.x;
        As[acol + 1][arow] = avv.y;
        As[acol + 2][arow] = avv.z;
        As[acol + 3][arow] = avv.w;
        *(float4*)(&Bs[brow][bcol]) = bvv;
        __syncthreads();
#pragma unroll
        for (int kk = 0; kk < 16; ++kk) {
            float4 a = *(const float4*)(&As[kk][ty << 2]);
            float4 b = *(const float4*)(&Bs[kk][tx << 2]);
            acc00 = fmaf(a.x, b.x, acc00); acc01 = fmaf(a.x, b.y, acc01);
            acc02 = fmaf(a.x, b.z, acc02); acc03 = fmaf(a.x, b.w, acc03);
            acc10 = fmaf(a.y, b.x, acc10); acc11 = fmaf(a.y, b.y, acc11);
            acc12 = fmaf(a.y, b.z, acc12); acc13 = fmaf(a.y, b.w, acc13);
            acc20 = fmaf(a.z, b.x, acc20); acc21 = fmaf(a.z, b.y, acc21);
            acc22 = fmaf(a.z, b.z, acc22); acc23 = fmaf(a.z, b.w, acc23);
            acc30 = fmaf(a.w, b.x, acc30); acc31 = fmaf(a.w, b.y, acc31);
            acc32 = fmaf(a.w, b.z, acc32); acc33 = fmaf(a.w, b.w, acc33);
        }
        __syncthreads();
    }

    float accs[4][4] = {{acc00,acc01,acc02,acc03},{acc10,acc11,acc12,acc13},
                        {acc20,acc21,acc22,acc23},{acc30,acc31,acc32,acc33}};
#pragma unroll
    for (int i = 0; i < 4; ++i) {
        int r = bm + (ty << 2) + i;
#pragma unroll
        for (int j = 0; j < 4; ++j) {
            int c = bn + (tx << 2) + j;
            float vv = accs[i][j];
            if (bias) vv += bias[c];
            if (doRelu) vv = fmaxf(vv, 0.f);
            C[(size_t)r * ldc + c] = vv;
        }
    }
}

// ---------------- position packing: (x, y, z, |p|^2) ----------------
__global__ void pack_pos(const float* __restrict__ pos, float4* __restrict__ out, int n)
{
    int i = blockIdx.x * blockDim.x + threadIdx.x;
    if (i >= n) return;
    float x = pos[i * 3 + 0], y = pos[i * 3 + 1], z = pos[i * 3 + 2];
    out[i] = make_float4(x, y, z, x * x + y * y + z * z);
}

// ---------------- pack wq|wk|wv -> [L,128,384] ----------------
__global__ void pack_qkv(const float* __restrict__ wq, const float* __restrict__ wk,
                         const float* __restrict__ wv, float* __restrict__ out)
{
    int i = blockIdx.x * blockDim.x + threadIdx.x;
    if (i >= LTOT * ADIM * ADIM) return;
    int li = i / (ADIM * ADIM);
    int r = (i / ADIM) % ADIM;
    int c = i % ADIM;
    float* o = out + ((size_t)li * ADIM + r) * QKVS;
    o[c] = wq[i];
    o[ADIM + c] = wk[i];
    o[2 * ADIM + c] = wv[i];
}

// ---------------- strided copy of vox h0 into feat cols [0:128) ----------------
__global__ void copy_to_feat(const float* __restrict__ src, float* __restrict__ feat)
{
    int i = blockIdx.x * blockDim.x + threadIdx.x;
    if (i >= NV * ADIM) return;
    int r = i >> 7, c = i & 127;
    feat[(size_t)r * 640 + c] = src[i];
}

// ---------------- brute-force KNN: warp per dst, smem-tiled packed src positions
// reproduces reference d2 = |a|^2 + |b|^2 - 2 a.b and top_k stable (d2, idx) ordering
template <int KK, bool EXCL>
__global__ void knn_kernel(const float* __restrict__ dpos, const float4* __restrict__ spos4,
                           int Ns, int* __restrict__ outIdx)
{
    const int TS = 1024;
    __shared__ float4 s4[TS];
    int lane = threadIdx.x & 31;
    int dst = (blockIdx.x << 3) + (threadIdx.x >> 5);

    float px = dpos[dst * 3 + 0], py = dpos[dst * 3 + 1], pz = dpos[dst * 3 + 2];
    float sa = px * px + py * py + pz * pz;

    float bd[KK]; int bi[KK];
#pragma unroll
    for (int p = 0; p < KK; ++p) { bd[p] = 3.0e38f; bi[p] = 0x7fffffff; }

    for (int t0 = 0; t0 < Ns; t0 += TS) {
        int tn = Ns - t0; if (tn > TS) tn = TS;
        __syncthreads();
        for (int i = threadIdx.x; i < tn; i += 256) s4[i] = spos4[t0 + i];
        __syncthreads();
#pragma unroll 4
        for (int j = lane; j < tn; j += 32) {
            int si = t0 + j;
            if (EXCL && si == dst) continue;
            float4 qv = s4[j];
            float dot = fmaf(pz, qv.z, fmaf(py, qv.y, px * qv.x));
            float d2 = (sa + qv.w) - 2.0f * dot;
            if (d2 < bd[KK - 1] || (d2 == bd[KK - 1] && si < bi[KK - 1])) {
                bd[KK - 1] = d2; bi[KK - 1] = si;
#pragma unroll
                for (int p = KK - 1; p > 0; --p) {
                    bool sw = (bd[p] < bd[p - 1]) || (bd[p] == bd[p - 1] && bi[p] < bi[p - 1]);
                    if (sw) {
                        float td = bd[p]; bd[p] = bd[p - 1]; bd[p - 1] = td;
                        int   ti = bi[p]; bi[p] = bi[p - 1]; bi[p - 1] = ti;
                    }
                }
            }
        }
    }
    // warp merge of 32 sorted lane lists -> global KK smallest (lexicographic)
    for (int r = 0; r < KK; ++r) {
        float cd = bd[0]; int ci = bi[0]; int cl = lane;
#pragma unroll
        for (int off = 16; off > 0; off >>= 1) {
            float od = __shfl_xor_sync(0xffffffffu, cd, off);
            int oi = __shfl_xor_sync(0xffffffffu, ci, off);
            int ol = __shfl_xor_sync(0xffffffffu, cl, off);
            if (od < cd || (od == cd && oi < ci)) { cd = od; ci = oi; cl = ol; }
        }
        if (lane == 0) outIdx[dst * KK + r] = ci;
        if (lane == cl) {
#pragma unroll
            for (int p = 0; p < KK - 1; ++p) { bd[p] = bd[p + 1]; bi[p] = bi[p + 1]; }
            bd[KK - 1] = 3.0e38f; bi[KK - 1] = 0x7fffffff;
        }
    }
}

// ---------------- per-row 128->8 projection (edge MLP first layer halves)
// warp per row; W is [128,8] row-major slice (row stride 8)
__global__ void proj8_kernel(const float* __restrict__ H, int Nrows,
                             const float* __restrict__ W, float* __restrict__ out)
{
    int w = (blockIdx.x * blockDim.x + threadIdx.x) >> 5;
    int lane = threadIdx.x & 31;
    if (w >= Nrows) return;
    const float* hr = H + (size_t)w * ADIM;
    float acc[8];
#pragma unroll
    for (int m = 0; m < 8; ++m) acc[m] = 0.f;
    for (int f = lane; f < ADIM; f += 32) {
        float hv = hr[f];
        const float* wr = W + f * 8;
#pragma unroll
        for (int m = 0; m < 8; ++m) acc[m] = fmaf(hv, wr[m], acc[m]);
    }
#pragma unroll
    for (int off = 16; off > 0; off >>= 1) {
#pragma unroll
        for (int m = 0; m < 8; ++m) acc[m] += __shfl_xor_sync(0xffffffffu, acc[m], off);
    }
    if (lane == 0) {
#pragma unroll
        for (int m = 0; m < 8; ++m) out[w * 8 + m] = acc[m];
    }
}

// ---------------- edge weight MLP (decomposed) + unified neighbor table write
__global__ void edgew_kernel(const int* __restrict__ nbr, int E, int Kk,
                             const float* __restrict__ dstPos, const float* __restrict__ srcPos,
                             const float* __restrict__ pSrc, const float* __restrict__ pDst,
                             const float* __restrict__ w1d, const float* __restrict__ b1,
                             const float* __restrict__ w2, const float* __restrict__ b2v,
                             int* __restrict__ Uidx, float* __restrict__ Uew,
                             int dstNodeBase, int slotOff, int srcGlobalOff)
{
    int e = blockIdx.x * blockDim.x + threadIdx.x;
    if (e >= E) return;
    int dl = e / Kk, slot = e - dl * Kk;
    int s = nbr[e];
    float dx = dstPos[dl * 3 + 0] - srcPos[s * 3 + 0];
    float dy = dstPos[dl * 3 + 1] - srcPos[s * 3 + 1];
    float dz = dstPos[dl * 3 + 2] - srcPos[s * 3 + 2];
    float ss = fmaf(dz, dz, fmaf(dy, dy, dx * dx));
    float d = sqrtf(ss + 1e-12f);
    float ew = b2v[0];
#pragma unroll
    for (int m = 0; m < 8; ++m) {
        float hmid = pSrc[s * 8 + m] + pDst[dl * 8 + m] + d * w1d[m] + b1[m];
        ew = fmaf(fmaxf(hmid, 0.f), w2[m], ew);
    }
    int un = dstNodeBase + dl;
    Uidx[un * MAXDEG + slotOff + slot] = srcGlobalOff + s;
    Uew[un * MAXDEG + slotOff + slot] = ew;
}

// ---------------- fused attention + residual + LayerNorm (+optional snapshot)
// one block (128 threads = 4 head-warps) per dst node; q|k|v packed row stride 384
__global__ void attn_kernel(const float* __restrict__ qkv,
                            const int* __restrict__ Uidx, const float* __restrict__ Uew,
                            float* __restrict__ h,
                            const float* __restrict__ lng, const float* __restrict__ lnb,
                            float* __restrict__ snap)   // stride 640 if non-null
{
    __shared__ float kvs[2 * MAXDEG][133];   // rows [0,deg): k, rows [MAXDEG, MAXDEG+deg): v
    __shared__ float qs[ADIM];
    __shared__ int   srcs[MAXDEG];
    __shared__ float ews[MAXDEG];
    __shared__ float red[8];

    int n = blockIdx.x;
    int t = threadIdx.x;
    int head = t >> 5, lane = t & 31;
    int deg = (n < NA) ? KAA : MAXDEG;

    if (t < deg) { srcs[t] = Uidx[n * MAXDEG + t]; ews[t] = Uew[n * MAXDEG + t]; }
    qs[t] = qkv[(size_t)n * QKVS + t];
    __syncthreads();

    // single staging pass: k and v rows of all neighbors (coalesced, 2*deg loads in flight)
#pragma unroll 5
    for (int j = 0; j < deg; ++j) {
        const float* base = qkv + (size_t)srcs[j] * QKVS;
        kvs[j][t] = base[ADIM + t];
        kvs[MAXDEG + j][t] = base[2 * ADIM + t];
    }
    __syncthreads();

    // logits: lane j of each head-warp handles neighbor j
    float logit = -3.0e38f;
    if (lane < deg) {
        const float* kr = &kvs[lane][head << 5];
        const float* qr = &qs[head << 5];
        float acc = 0.f;
#pragma unroll
        for (int d = 0; d < 32; ++d) acc = fmaf(kr[d], qr[d], acc);
        logit = acc * 0.17677669529663687f + ews[lane];
    }
    float m = logit;
#pragma unroll
    for (int off = 16; off > 0; off >>= 1)
        m = fmaxf(m, __shfl_xor_sync(0xffffffffu, m, off));
    float z = (lane < deg) ? expf(logit - m) : 0.f;
    float ssum = z;
#pragma unroll
    for (int off = 16; off > 0; off >>= 1)
        ssum += __shfl_xor_sync(0xffffffffu, ssum, off);
    float alpha = z / (ssum + 1e-9f);

    float acc = 0.f;
    for (int j = 0; j < deg; ++j) {
        float a = __shfl_sync(0xffffffffu, alpha, j);
        acc = fmaf(a, kvs[MAXDEG + j][(head << 5) + lane], acc);
    }

    // residual + LN
    float y = h[(size_t)n * ADIM + t] + acc;
    float s1 = y, s2 = y * y;
#pragma unroll
    for (int off = 16; off > 0; off >>= 1) {
        s1 += __shfl_xor_sync(0xffffffffu, s1, off);
        s2 += __shfl_xor_sync(0xffffffffu, s2, off);
    }
    if (lane == 0) { red[head] = s1; red[4 + head] = s2; }
    __syncthreads();
    float t1 = red[0] + red[1] + red[2] + red[3];
    float t2 = red[4] + red[5] + red[6] + red[7];
    float mu = t1 * (1.0f / ADIM);
    float var = fmaxf(t2 * (1.0f / ADIM) - mu * mu, 0.f);
    float outv = (y - mu) * rsqrtf(var + 1e-5f) * lng[t] + lnb[t];
    h[(size_t)n * ADIM + t] = outv;
    if (snap != nullptr && n >= NA) snap[(size_t)(n - NA) * 640 + t] = outv;
}

// ---------------- host ----------------
extern "C" void kernel_launch(void* const* d_in, const int* in_sizes, int n_in,
                              void* d_out, int out_size)
{
    const float* atom_x    = (const float*)d_in[0];
    const float* atom_pos  = (const float*)d_in[1];
    const float* vox_x     = (const float*)d_in[2];
    const float* vox_pos   = (const float*)d_in[3];
    const float* w_atom_in = (const float*)d_in[4];
    const float* b_atom_in = (const float*)d_in[5];
    const float* w_vox_in  = (const float*)d_in[6];
    const float* b_vox_in  = (const float*)d_in[7];
    const float* aa_w1 = (const float*)d_in[8];
    const float* aa_b1 = (const float*)d_in[9];
    const float* aa_w2 = (const float*)d_in[10];
    const float* aa_b2 = (const float*)d_in[11];
    const float* av_w1 = (const float*)d_in[12];
    const float* av_b1 = (const float*)d_in[13];
    const float* av_w2 = (const float*)d_in[14];
    const float* av_b2 = (const float*)d_in[15];
    const float* vv_w1 = (const float*)d_in[16];
    const float* vv_b1 = (const float*)d_in[17];
    const float* vv_w2 = (const float*)d_in[18];
    const float* vv_b2 = (const float*)d_in[19];
    const float* wq   = (const float*)d_in[20];
    const float* wk   = (const float*)d_in[21];
    const float* wv   = (const float*)d_in[22];
    const float* ln_g = (const float*)d_in[23];
    const float* ln_b = (const float*)d_in[24];
    const float* w_o1 = (const float*)d_in[25];
    const float* b_o1 = (const float*)d_in[26];
    const float* w_o2 = (const float*)d_in[27];
    const float* b_o2 = (const float*)d_in[28];
    float* out = (float*)d_out;
    (void)in_sizes; (void)n_in; (void)out_size;

    float *h, *qkv, *wqkv, *Uew, *paas, *paad, *pavd, *pavs, *pvvs, *pvvd, *feat, *hidden;
    float4 *apos4, *vpos4;
    int *aaIdx, *avIdx, *vvIdx, *Uidx;
    cudaGetSymbolAddress((void**)&h, g_h);
    cudaGetSymbolAddress((void**)&qkv, g_qkv);
    cudaGetSymbolAddress((void**)&wqkv, g_wqkv);
    cudaGetSymbolAddress((void**)&apos4, g_apos4);
    cudaGetSymbolAddress((void**)&vpos4, g_vpos4);
    cudaGetSymbolAddress((void**)&aaIdx, g_aa);
    cudaGetSymbolAddress((void**)&avIdx, g_av);
    cudaGetSymbolAddress((void**)&vvIdx, g_vv);
    cudaGetSymbolAddress((void**)&Uidx, g_Uidx);
    cudaGetSymbolAddress((void**)&Uew, g_Uew);
    cudaGetSymbolAddress((void**)&paas, g_paas);
    cudaGetSymbolAddress((void**)&paad, g_paad);
    cudaGetSymbolAddress((void**)&pavd, g_pavd);
    cudaGetSymbolAddress((void**)&pavs, g_pavs);
    cudaGetSymbolAddress((void**)&pvvs, g_pvvs);
    cudaGetSymbolAddress((void**)&pvvd, g_pvvd);
    cudaGetSymbolAddress((void**)&feat, g_feat);
    cudaGetSymbolAddress((void**)&hidden, g_hidden);

    const float* voxh0 = h + (size_t)NA * ADIM;   // valid until layer loop mutates h

    // 0) packing
    pack_pos<<<(NA + 255) / 256, 256>>>(atom_pos, apos4, NA);
    pack_pos<<<(NV + 255) / 256, 256>>>(vox_pos, vpos4, NV);
    pack_qkv<<<(LTOT * ADIM * ADIM + 255) / 256, 256>>>(wq, wk, wv, wqkv);

    // 1) input projections -> h (atoms then voxels); stash vox_h0 into feat[:,0:128]
    gemm64<<<dim3(NA / 64, ADIM / 64), 256>>>(atom_x, w_atom_in, b_atom_in, h, FDIM, ADIM, 0, ADIM);
    gemm64<<<dim3(NV / 64, ADIM / 64), 256>>>(vox_x, w_vox_in, b_vox_in, (float*)voxh0, FDIM, ADIM, 0, ADIM);
    copy_to_feat<<<(NV * ADIM + 255) / 256, 256>>>(voxh0, feat);

    // 2) KNN graphs
    knn_kernel<KAA, true><<<NA / 8, 256>>>(atom_pos, apos4, NA, aaIdx);
    knn_kernel<KVV, false><<<NV / 8, 256>>>(vox_pos, apos4, NA, avIdx);
    knn_kernel<KVV, true><<<NV / 8, 256>>>(vox_pos, vpos4, NV, vvIdx);

    // 3) edge-MLP first-layer projections (top half of W1 = i0 features, bottom = i1)
    proj8_kernel<<<NA / 8, 256>>>(h, NA, aa_w1, paas);                 // aa: i0 = src atom
    proj8_kernel<<<NA / 8, 256>>>(h, NA, aa_w1 + 128 * 8, paad);       // aa: i1 = dst atom
    proj8_kernel<<<NV / 8, 256>>>(voxh0, NV, av_w1, pavd);             // av: i0 = vox (dst)
    proj8_kernel<<<NA / 8, 256>>>(h, NA, av_w1 + 128 * 8, pavs);       // av: i1 = atom (src)
    proj8_kernel<<<NV / 8, 256>>>(voxh0, NV, vv_w1, pvvs);             // vv: i0 = src vox
    proj8_kernel<<<NV / 8, 256>>>(voxh0, NV, vv_w1 + 128 * 8, pvvd);   // vv: i1 = dst vox

    // 4) edge weights + unified neighbor table
    edgew_kernel<<<(NA * KAA + 255) / 256, 256>>>(aaIdx, NA * KAA, KAA, atom_pos, atom_pos,
        paas, paad, aa_w1 + 256 * 8, aa_b1, aa_w2, aa_b2, Uidx, Uew, 0, 0, 0);
    edgew_kernel<<<(NV * KVV + 255) / 256, 256>>>(avIdx, NV * KVV, KVV, vox_pos, atom_pos,
        pavs, pavd, av_w1 + 256 * 8, av_b1, av_w2, av_b2, Uidx, Uew, NA, 0, 0);
    edgew_kernel<<<(NV * KVV + 255) / 256, 256>>>(vvIdx, NV * KVV, KVV, vox_pos, vox_pos,
        pvvs, pvvd, vv_w1 + 256 * 8, vv_b1, vv_w2, vv_b2, Uidx, Uew, NA, KVV, NA);

    // 5) attention stack (8 layers), fused QKV GEMM, snapshot vox rows into feat
    for (int li = 0; li < LTOT; ++li) {
        gemm64<<<dim3(NN / 64, QKVS / 64), 256>>>(h, wqkv + (size_t)li * ADIM * QKVS,
                                                  nullptr, qkv, ADIM, QKVS, 0, QKVS);
        float* snap = (li & 1) ? (feat + (size_t)((li >> 1) + 1) * ADIM) : nullptr;
        attn_kernel<<<NN, 128>>>(qkv, Uidx, Uew, h,
                                 ln_g + (size_t)li * ADIM, ln_b + (size_t)li * ADIM, snap);
    }

    // 6) output head: feat [NV,640] -> relu -> [NV,128] -> [NV,128]
    gemm64<<<dim3(NV / 64, ADIM / 64), 256>>>(feat, w_o1, b_o1, hidden, 640, ADIM, 1, ADIM);
    gemm64<<<dim3(NV / 64, OUTD / 64), 256>>>(hidden, w_o2, b_o2, out, ADIM, OUTD, 0, OUTD);
}